// round 2
// baseline (speedup 1.0000x reference)
#include <cuda_runtime.h>
#include <math.h>

#define Bb 2
#define Tt 1024
#define Cc 2048
#define Hh 32
#define Dd 64
#define NT (Bb*Tt)        /* 2048 token rows */
#define L3 96             /* 3 * D_MIX_LORA */

// ---------------- scratch (device globals; allocation-free) ----------------
__device__ __align__(16) float s_dx[NT*Cc];
__device__ __align__(16) float s_xx[NT*Cc];
__device__ __align__(16) float s_h [NT*L3];
__device__ __align__(16) float s_xr[NT*Cc];
__device__ __align__(16) float s_xk[NT*Cc];
__device__ __align__(16) float s_xv[NT*Cc];
__device__ __align__(16) float s_yq[NT*Cc];
__device__ __align__(16) float s_yk[NT*Cc];
__device__ __align__(16) float s_yv[NT*Cc];
__device__ __align__(16) float s_qh[NT*Cc];   // [B,H,T,D]
__device__ __align__(16) float s_kh[NT*Cc];
__device__ __align__(16) float s_vh[NT*Cc];
__device__ __align__(16) float s_att[NT*Cc];  // [B,T,C]
__device__ __align__(16) float s_on[NT*Cc];

// ---------------- 1. shift + token-mix base ----------------
__global__ __launch_bounds__(256) void k_prelude(
    const float* __restrict__ x, const float* __restrict__ shift,
    const float* __restrict__ maa_x)
{
    int idx = blockIdx.x * 256 + threadIdx.x;      // over NT*Cc exactly
    int c  = idx & (Cc - 1);
    int bt = idx >> 11;
    int t  = bt & (Tt - 1);
    int b  = bt >> 10;
    float xv = x[idx];
    float xp = (t == 0) ? shift[b*Cc + c] : x[idx - Cc];
    float dx = xp - xv;
    s_dx[idx] = dx;
    s_xx[idx] = fmaf(dx, maa_x[c], xv);
}

// ---------------- 2. LoRA stage 1: h = tanh(xx @ w1)  [NT,96] ----------------
__global__ __launch_bounds__(96) void k_lora1(const float* __restrict__ w1)
{
    __shared__ float xs[16][128];
    int n0 = blockIdx.x * 16;
    int j  = threadIdx.x;                          // 0..95 output column
    float acc[16];
#pragma unroll
    for (int r = 0; r < 16; r++) acc[r] = 0.f;
    for (int k0 = 0; k0 < Cc; k0 += 128) {
        __syncthreads();
        for (int i = threadIdx.x; i < 16*128; i += 96) {
            int r = i >> 7, cc = i & 127;
            xs[r][cc] = s_xx[(n0 + r)*Cc + k0 + cc];
        }
        __syncthreads();
        for (int k = 0; k < 128; k++) {
            float wv = w1[(k0 + k)*L3 + j];
#pragma unroll
            for (int r = 0; r < 16; r++) acc[r] = fmaf(xs[r][k], wv, acc[r]);
        }
    }
#pragma unroll
    for (int r = 0; r < 16; r++) s_h[(n0 + r)*L3 + j] = tanhf(acc[r]);
}

// ---------------- 3. LoRA stage 2 + mixing: xr/xk/xv ----------------
__global__ __launch_bounds__(64) void k_mix(
    const float* __restrict__ x, const float* __restrict__ w2,
    const float* __restrict__ maa_r, const float* __restrict__ maa_k,
    const float* __restrict__ maa_v)
{
    __shared__ float w2s[96][64];
    __shared__ float hs[16][96];
    int c0 = blockIdx.x * 64;
    int n0 = blockIdx.y * 16;
    int tid = threadIdx.x;
    for (int i = tid; i < 96*64; i += 64) {
        int rr = i >> 6, cc = i & 63;
        w2s[rr][cc] = w2[rr*Cc + c0 + cc];
    }
    for (int i = tid; i < 16*96; i += 64) {
        int rr = i / 96, jj = i % 96;
        hs[rr][jj] = s_h[(n0 + rr)*L3 + jj];
    }
    __syncthreads();
    int c = c0 + tid;
    float ar = maa_r[c], ak = maa_k[c], av = maa_v[c];
    for (int r = 0; r < 16; r++) {
        float m0 = 0.f, m1 = 0.f, m2 = 0.f;
#pragma unroll
        for (int i = 0; i < 32; i++) {
            m0 = fmaf(hs[r][i],      w2s[i][tid],      m0);
            m1 = fmaf(hs[r][32 + i], w2s[32 + i][tid], m1);
            m2 = fmaf(hs[r][64 + i], w2s[64 + i][tid], m2);
        }
        size_t idx = (size_t)(n0 + r)*Cc + c;
        float xf = x[idx], dxf = s_dx[idx];
        s_xr[idx] = fmaf(dxf, ar + m0, xf);
        s_xk[idx] = fmaf(dxf, ak + m1, xf);
        s_xv[idx] = fmaf(dxf, av + m2, xf);
    }
}

// ---------------- SGEMM core: 2048x2048x2048, 128x128x8 tiles ----------------
__device__ __forceinline__ void gemm2048(
    const float* __restrict__ A, const float* __restrict__ Bm,
    float* __restrict__ Cm)
{
    const int K = Cc, N = Cc;
    __shared__ __align__(16) float As[8][128];
    __shared__ __align__(16) float Bs[8][128];
    int tid = threadIdx.x;
    int tx = tid & 15, ty = tid >> 4;
    int aRow = tid >> 1, aCol = (tid & 1) << 2;
    int bRow = tid >> 5, bCol = (tid & 31) << 2;
    const float* Aptr = A + (size_t)(blockIdx.y*128 + aRow)*K + aCol;
    const float* Bptr = Bm + (size_t)bRow*N + blockIdx.x*128 + bCol;
    float acc[8][8];
#pragma unroll
    for (int i = 0; i < 8; i++)
#pragma unroll
        for (int j = 0; j < 8; j++) acc[i][j] = 0.f;

    float4 a4 = *(const float4*)Aptr;
    float4 b4 = *(const float4*)Bptr;
    for (int k0 = 0; k0 < K; k0 += 8) {
        As[aCol + 0][aRow] = a4.x; As[aCol + 1][aRow] = a4.y;
        As[aCol + 2][aRow] = a4.z; As[aCol + 3][aRow] = a4.w;
        *(float4*)&Bs[bRow][bCol] = b4;
        __syncthreads();
        if (k0 + 8 < K) {                        // prefetch next tiles
            Aptr += 8; Bptr += (size_t)8*N;
            a4 = *(const float4*)Aptr;
            b4 = *(const float4*)Bptr;
        }
#pragma unroll
        for (int k = 0; k < 8; k++) {
            float4 a0 = *(const float4*)&As[k][ty << 2];
            float4 a1 = *(const float4*)&As[k][64 + (ty << 2)];
            float4 b0 = *(const float4*)&Bs[k][tx << 2];
            float4 b1 = *(const float4*)&Bs[k][64 + (tx << 2)];
            float arr[8] = {a0.x,a0.y,a0.z,a0.w,a1.x,a1.y,a1.z,a1.w};
            float brr[8] = {b0.x,b0.y,b0.z,b0.w,b1.x,b1.y,b1.z,b1.w};
#pragma unroll
            for (int i = 0; i < 8; i++)
#pragma unroll
                for (int j = 0; j < 8; j++)
                    acc[i][j] = fmaf(arr[i], brr[j], acc[i][j]);
        }
        __syncthreads();
    }
#pragma unroll
    for (int i = 0; i < 8; i++) {
        int r = blockIdx.y*128 + ((i < 4) ? (ty*4 + i) : (64 + ty*4 + i - 4));
        float* Cp = Cm + (size_t)r*N + blockIdx.x*128;
        *(float4*)(Cp + (tx << 2))      = make_float4(acc[i][0],acc[i][1],acc[i][2],acc[i][3]);
        *(float4*)(Cp + 64 + (tx << 2)) = make_float4(acc[i][4],acc[i][5],acc[i][6],acc[i][7]);
    }
}

__global__ __launch_bounds__(256) void k_gemm_qkv(
    const float* __restrict__ Wq, const float* __restrict__ Wk,
    const float* __restrict__ Wv)
{
    const float* A; const float* W; float* C;
    if (blockIdx.z == 0)      { A = s_xr; W = Wq; C = s_yq; }
    else if (blockIdx.z == 1) { A = s_xk; W = Wk; C = s_yk; }
    else                      { A = s_xv; W = Wv; C = s_yv; }
    gemm2048(A, W, C);
}

__global__ __launch_bounds__(256) void k_gemm_o(
    const float* __restrict__ Wo, float* __restrict__ out)
{
    gemm2048(s_on, Wo, out);
}

// ---------------- 4. LN (+RoPE) into head layout ----------------
__global__ __launch_bounds__(256) void k_lnqkv(
    const float* __restrict__ gr, const float* __restrict__ br_,
    const float* __restrict__ gk, const float* __restrict__ bk_,
    const float* __restrict__ gv, const float* __restrict__ bv_,
    const float* __restrict__ cosT, const float* __restrict__ sinT)
{
    int mode = blockIdx.y;
    const float* Y; const float* g; const float* bbv; float* out;
    if (mode == 0)      { Y = s_yq; g = gr; bbv = br_; out = s_qh; }
    else if (mode == 1) { Y = s_yk; g = gk; bbv = bk_; out = s_kh; }
    else                { Y = s_yv; g = gv; bbv = bv_; out = s_vh; }
    int row = blockIdx.x;
    int t = row & (Tt - 1), b = row >> 10;
    __shared__ float srow[Cc];
    __shared__ float red[64];
    const float* yr = Y + (size_t)row*Cc;
    float sum = 0.f, sq = 0.f, vals[8];
#pragma unroll
    for (int k = 0; k < 8; k++) {
        float v = yr[threadIdx.x + k*256];
        vals[k] = v; sum += v; sq = fmaf(v, v, sq);
    }
#pragma unroll
    for (int o = 16; o; o >>= 1) {
        sum += __shfl_xor_sync(0xffffffffu, sum, o);
        sq  += __shfl_xor_sync(0xffffffffu, sq,  o);
    }
    int w = threadIdx.x >> 5;
    if ((threadIdx.x & 31) == 0) { red[w] = sum; red[32 + w] = sq; }
    __syncthreads();
    if (threadIdx.x < 32) {
        float s1 = (threadIdx.x < 8) ? red[threadIdx.x] : 0.f;
        float s2 = (threadIdx.x < 8) ? red[32 + threadIdx.x] : 0.f;
#pragma unroll
        for (int o = 4; o; o >>= 1) {
            s1 += __shfl_xor_sync(0xffffffffu, s1, o);
            s2 += __shfl_xor_sync(0xffffffffu, s2, o);
        }
        if (threadIdx.x == 0) { red[0] = s1; red[32] = s2; }
    }
    __syncthreads();
    float mu  = red[0]  * (1.f/Cc);
    float var = red[32] * (1.f/Cc) - mu*mu;
    float inv = rsqrtf(var + 1e-5f);
#pragma unroll
    for (int k = 0; k < 8; k++) {
        int c = threadIdx.x + k*256;
        srow[c] = (vals[k] - mu)*inv*g[c] + bbv[c];
    }
    __syncthreads();
#pragma unroll
    for (int k = 0; k < 8; k++) {
        int c = threadIdx.x + k*256;
        int h = c >> 6, d = c & 63;
        float o;
        if (mode == 2) { o = srow[c]; }
        else if (d < 32) {
            float cc = cosT[t*32 + d], ss = sinT[t*32 + d];
            o = srow[c]*cc - srow[c + 32]*ss;
        } else {
            int d2 = d - 32;
            float cc = cosT[t*32 + d2], ss = sinT[t*32 + d2];
            o = srow[c - 32]*ss + srow[c]*cc;
        }
        out[(((size_t)(b*Hh + h)*Tt + t) << 6) + d] = o;
    }
}

// ---------------- 6. LN of attention output (plain layout) ----------------
__global__ __launch_bounds__(256) void k_lnplain(
    const float* __restrict__ gx, const float* __restrict__ bx)
{
    int row = blockIdx.x;
    __shared__ float red[64];
    const float* yr = s_att + (size_t)row*Cc;
    float sum = 0.f, sq = 0.f, vals[8];
#pragma unroll
    for (int k = 0; k < 8; k++) {
        float v = yr[threadIdx.x + k*256];
        vals[k] = v; sum += v; sq = fmaf(v, v, sq);
    }
#pragma unroll
    for (int o = 16; o; o >>= 1) {
        sum += __shfl_xor_sync(0xffffffffu, sum, o);
        sq  += __shfl_xor_sync(0xffffffffu, sq,  o);
    }
    int w = threadIdx.x >> 5;
    if ((threadIdx.x & 31) == 0) { red[w] = sum; red[32 + w] = sq; }
    __syncthreads();
    if (threadIdx.x < 32) {
        float s1 = (threadIdx.x < 8) ? red[threadIdx.x] : 0.f;
        float s2 = (threadIdx.x < 8) ? red[32 + threadIdx.x] : 0.f;
#pragma unroll
        for (int o = 4; o; o >>= 1) {
            s1 += __shfl_xor_sync(0xffffffffu, s1, o);
            s2 += __shfl_xor_sync(0xffffffffu, s2, o);
        }
        if (threadIdx.x == 0) { red[0] = s1; red[32] = s2; }
    }
    __syncthreads();
    float mu  = red[0]  * (1.f/Cc);
    float var = red[32] * (1.f/Cc) - mu*mu;
    float inv = rsqrtf(var + 1e-5f);
    float* orow = s_on + (size_t)row*Cc;
#pragma unroll
    for (int k = 0; k < 8; k++) {
        int c = threadIdx.x + k*256;
        orow[c] = (vals[k] - mu)*inv*gx[c] + bx[c];
    }
}

// ---------------- 5. causal flash attention, fp32, BM=64 BN=32 ----------------
__global__ __launch_bounds__(256) void k_attn()
{
    __shared__ __align__(16) float Qs[64][68];
    __shared__ __align__(16) float Kt[64][34];   // transposed K: [d][s]
    __shared__ __align__(16) float Vs[32][64];
    __shared__ float Ps[64][33];
    int qt = (int)gridDim.x - 1 - (int)blockIdx.x;   // heavy tiles first
    int bh = blockIdx.y;
    const float* Qg = s_qh + (size_t)bh*Tt*64;
    const float* Kg = s_kh + (size_t)bh*Tt*64;
    const float* Vg = s_vh + (size_t)bh*Tt*64;
    int b = bh >> 5, h = bh & 31;
    int tid = threadIdx.x, tx = tid & 15, ty = tid >> 4;
    int q0 = qt * 64;

    for (int i = tid; i < 64*16; i += 256) {
        int r = i >> 4, c4 = (i & 15) << 2;
        *(float4*)&Qs[r][c4] = *(const float4*)(Qg + (size_t)(q0 + r)*64 + c4);
    }
    float accO[4][4];
    float mrow[4], lrow[4];
#pragma unroll
    for (int i = 0; i < 4; i++) {
        mrow[i] = -1e30f; lrow[i] = 0.f;
#pragma unroll
        for (int j = 0; j < 4; j++) accO[i][j] = 0.f;
    }
    __syncthreads();

    int nkb = (qt + 1) * 2;
    for (int kb = 0; kb < nkb; kb++) {
        int s0 = kb * 32;
        for (int i = tid; i < 32*16; i += 256) {
            int r = i >> 4, c4 = (i & 15) << 2;
            float4 kv = *(const float4*)(Kg + (size_t)(s0 + r)*64 + c4);
            Kt[c4 + 0][r] = kv.x; Kt[c4 + 1][r] = kv.y;
            Kt[c4 + 2][r] = kv.z; Kt[c4 + 3][r] = kv.w;
            *(float4*)&Vs[r][c4] = *(const float4*)(Vg + (size_t)(s0 + r)*64 + c4);
        }
        __syncthreads();

        float sc[4][2];
#pragma unroll
        for (int i = 0; i < 4; i++) { sc[i][0] = 0.f; sc[i][1] = 0.f; }
#pragma unroll 4
        for (int d = 0; d < 64; d++) {
            float2 kv = *(const float2*)&Kt[d][tx << 1];
#pragma unroll
            for (int i = 0; i < 4; i++) {
                float qv = Qs[ty*4 + i][d];
                sc[i][0] = fmaf(qv, kv.x, sc[i][0]);
                sc[i][1] = fmaf(qv, kv.y, sc[i][1]);
            }
        }
#pragma unroll
        for (int i = 0; i < 4; i++) {
            int qg = q0 + ty*4 + i;
            float s0v = sc[i][0] * 0.125f;
            float s1v = sc[i][1] * 0.125f;
            int kg0 = s0 + (tx << 1);
            if (kg0     > qg) s0v = -1e30f;
            if (kg0 + 1 > qg) s1v = -1e30f;
            float mx = fmaxf(s0v, s1v);
#pragma unroll
            for (int o = 8; o; o >>= 1) mx = fmaxf(mx, __shfl_xor_sync(0xffffffffu, mx, o));
            float mnew = fmaxf(mrow[i], mx);
            float alpha = __expf(mrow[i] - mnew);
            mrow[i] = mnew;
            float p0 = __expf(s0v - mnew);
            float p1 = __expf(s1v - mnew);
            float rs = p0 + p1;
#pragma unroll
            for (int o = 8; o; o >>= 1) rs += __shfl_xor_sync(0xffffffffu, rs, o);
            lrow[i] = lrow[i]*alpha + rs;
#pragma unroll
            for (int j = 0; j < 4; j++) accO[i][j] *= alpha;
            Ps[ty*4 + i][(tx << 1)]     = p0;
            Ps[ty*4 + i][(tx << 1) + 1] = p1;
        }
        __syncthreads();
#pragma unroll 8
        for (int s_ = 0; s_ < 32; s_++) {
            float4 vv = *(const float4*)&Vs[s_][tx << 2];
#pragma unroll
            for (int i = 0; i < 4; i++) {
                float p = Ps[ty*4 + i][s_];
                accO[i][0] = fmaf(p, vv.x, accO[i][0]);
                accO[i][1] = fmaf(p, vv.y, accO[i][1]);
                accO[i][2] = fmaf(p, vv.z, accO[i][2]);
                accO[i][3] = fmaf(p, vv.w, accO[i][3]);
            }
        }
        __syncthreads();
    }
#pragma unroll
    for (int i = 0; i < 4; i++) {
        float inv = 1.f / lrow[i];
        int t = q0 + ty*4 + i;
        float* op = s_att + (size_t)(b*Tt + t)*Cc + h*64 + (tx << 2);
        *(float4*)op = make_float4(accO[i][0]*inv, accO[i][1]*inv,
                                   accO[i][2]*inv, accO[i][3]*inv);
    }
}

// ---------------- launch ----------------
extern "C" void kernel_launch(void* const* d_in, const int* in_sizes, int n_in,
                              void* d_out, int out_size)
{
    (void)in_sizes; (void)n_in; (void)out_size;
    const float* x     = (const float*)d_in[0];
    const float* shift = (const float*)d_in[1];
    const float* maa_x = (const float*)d_in[2];
    const float* maa_r = (const float*)d_in[3];
    const float* maa_k = (const float*)d_in[4];
    const float* maa_v = (const float*)d_in[5];
    const float* w1    = (const float*)d_in[6];
    const float* w2    = (const float*)d_in[7];
    const float* Wq    = (const float*)d_in[8];
    const float* Wk    = (const float*)d_in[9];
    const float* Wv    = (const float*)d_in[10];
    const float* Wo    = (const float*)d_in[11];
    const float* g_r   = (const float*)d_in[12];
    const float* b_r   = (const float*)d_in[13];
    const float* g_k   = (const float*)d_in[14];
    const float* b_k   = (const float*)d_in[15];
    const float* g_v   = (const float*)d_in[16];
    const float* b_v   = (const float*)d_in[17];
    const float* g_x   = (const float*)d_in[18];
    const float* b_x   = (const float*)d_in[19];
    const float* cosT  = (const float*)d_in[20];
    const float* sinT  = (const float*)d_in[21];
    float* out = (float*)d_out;

    k_prelude<<<NT*Cc/256, 256>>>(x, shift, maa_x);
    k_lora1<<<NT/16, 96>>>(w1);
    k_mix<<<dim3(Cc/64, NT/16), 64>>>(x, w2, maa_r, maa_k, maa_v);
    k_gemm_qkv<<<dim3(16, 16, 3), 256>>>(Wq, Wk, Wv);
    k_lnqkv<<<dim3(NT, 3), 256>>>(g_r, b_r, g_k, b_k, g_v, b_v, cosT, sinT);
    k_attn<<<dim3(16, Bb*Hh), 256>>>();
    k_lnplain<<<NT, 256>>>(g_x, b_x);
    k_gemm_o<<<dim3(16, 16), 256>>>(Wo, out);
}

// round 4
// speedup vs baseline: 1.5104x; 1.5104x over previous
#include <cuda_runtime.h>
#include <cuda_bf16.h>
#include <math.h>
#include <stdint.h>

#define Bb 2
#define Tt 1024
#define Cc 2048
#define Hh 32
#define Dd 64
#define NT (Bb*Tt)        /* 2048 token rows */
#define L3 96             /* 3 * D_MIX_LORA */

// ---------------- scratch (device globals; allocation-free) ----------------
__device__ __align__(16) float s_dx[NT*Cc];
__device__ __align__(16) float s_xx[NT*Cc];
__device__ __align__(16) float s_h [NT*L3];
__device__ __align__(16) float s_xr[NT*Cc];
__device__ __align__(16) float s_xk[NT*Cc];
__device__ __align__(16) float s_xv[NT*Cc];
__device__ __align__(16) float s_yq[NT*Cc];
__device__ __align__(16) float s_yk[NT*Cc];
__device__ __align__(16) float s_yv[NT*Cc];
__device__ __align__(16) float s_qh[NT*Cc];   // [B,H,T,D]
__device__ __align__(16) float s_kh[NT*Cc];
__device__ __align__(16) float s_vh[NT*Cc];
__device__ __align__(16) float s_att[NT*Cc];  // [B,T,C]
__device__ __align__(16) float s_on[NT*Cc];

// ---------------- 1. shift + token-mix base ----------------
__global__ __launch_bounds__(256) void k_prelude(
    const float* __restrict__ x, const float* __restrict__ shift,
    const float* __restrict__ maa_x)
{
    int idx = blockIdx.x * 256 + threadIdx.x;
    int c  = idx & (Cc - 1);
    int bt = idx >> 11;
    int t  = bt & (Tt - 1);
    int b  = bt >> 10;
    float xv = x[idx];
    float xp = (t == 0) ? shift[b*Cc + c] : x[idx - Cc];
    float dx = xp - xv;
    s_dx[idx] = dx;
    s_xx[idx] = fmaf(dx, maa_x[c], xv);
}

// ---------------- 2. LoRA stage 1 ----------------
__global__ __launch_bounds__(96) void k_lora1(const float* __restrict__ w1)
{
    __shared__ float xs[16][128];
    int n0 = blockIdx.x * 16;
    int j  = threadIdx.x;
    float acc[16];
#pragma unroll
    for (int r = 0; r < 16; r++) acc[r] = 0.f;
    for (int k0 = 0; k0 < Cc; k0 += 128) {
        __syncthreads();
        for (int i = threadIdx.x; i < 16*128; i += 96) {
            int r = i >> 7, cc = i & 127;
            xs[r][cc] = s_xx[(n0 + r)*Cc + k0 + cc];
        }
        __syncthreads();
        for (int k = 0; k < 128; k++) {
            float wv = w1[(k0 + k)*L3 + j];
#pragma unroll
            for (int r = 0; r < 16; r++) acc[r] = fmaf(xs[r][k], wv, acc[r]);
        }
    }
#pragma unroll
    for (int r = 0; r < 16; r++) s_h[(n0 + r)*L3 + j] = tanhf(acc[r]);
}

// ---------------- 3. LoRA stage 2 + mixing ----------------
__global__ __launch_bounds__(64) void k_mix(
    const float* __restrict__ x, const float* __restrict__ w2,
    const float* __restrict__ maa_r, const float* __restrict__ maa_k,
    const float* __restrict__ maa_v)
{
    __shared__ float w2s[96][64];
    __shared__ float hs[16][96];
    int c0 = blockIdx.x * 64;
    int n0 = blockIdx.y * 16;
    int tid = threadIdx.x;
    for (int i = tid; i < 96*64; i += 64) {
        int rr = i >> 6, cc = i & 63;
        w2s[rr][cc] = w2[rr*Cc + c0 + cc];
    }
    for (int i = tid; i < 16*96; i += 64) {
        int rr = i / 96, jj = i % 96;
        hs[rr][jj] = s_h[(n0 + rr)*L3 + jj];
    }
    __syncthreads();
    int c = c0 + tid;
    float ar = maa_r[c], ak = maa_k[c], av = maa_v[c];
    for (int r = 0; r < 16; r++) {
        float m0 = 0.f, m1 = 0.f, m2 = 0.f;
#pragma unroll
        for (int i = 0; i < 32; i++) {
            m0 = fmaf(hs[r][i],      w2s[i][tid],      m0);
            m1 = fmaf(hs[r][32 + i], w2s[32 + i][tid], m1);
            m2 = fmaf(hs[r][64 + i], w2s[64 + i][tid], m2);
        }
        size_t idx = (size_t)(n0 + r)*Cc + c;
        float xf = x[idx], dxf = s_dx[idx];
        s_xr[idx] = fmaf(dxf, ar + m0, xf);
        s_xk[idx] = fmaf(dxf, ak + m1, xf);
        s_xv[idx] = fmaf(dxf, av + m2, xf);
    }
}

// ============ tensor-core GEMM: C = A @ B, 2048^3, 3x-bf16 split ============
__device__ __forceinline__ uint32_t cvta_sm(const void* p) {
    return (uint32_t)__cvta_generic_to_shared(p);
}
__device__ __forceinline__ void ldsm_x4(uint32_t addr, uint32_t* r) {
    asm volatile("ldmatrix.sync.aligned.m8n8.x4.shared.b16 {%0,%1,%2,%3},[%4];"
        : "=r"(r[0]), "=r"(r[1]), "=r"(r[2]), "=r"(r[3]) : "r"(addr));
}
__device__ __forceinline__ void ldsm_x4t(uint32_t addr, uint32_t* r) {
    asm volatile("ldmatrix.sync.aligned.m8n8.x4.trans.shared.b16 {%0,%1,%2,%3},[%4];"
        : "=r"(r[0]), "=r"(r[1]), "=r"(r[2]), "=r"(r[3]) : "r"(addr));
}
__device__ __forceinline__ void mma_bf16(float* d, const uint32_t* a, const uint32_t* b) {
    asm volatile(
        "mma.sync.aligned.m16n8k16.row.col.f32.bf16.bf16.f32 "
        "{%0,%1,%2,%3},{%4,%5,%6,%7},{%8,%9},{%0,%1,%2,%3};"
        : "+f"(d[0]), "+f"(d[1]), "+f"(d[2]), "+f"(d[3])
        : "r"(a[0]), "r"(a[1]), "r"(a[2]), "r"(a[3]), "r"(b[0]), "r"(b[1]));
}
__device__ __forceinline__ uint32_t packbf(float x, float y) {
    __nv_bfloat162 h = __floats2bfloat162_rn(x, y);
    return *(uint32_t*)&h;
}

// smem: A region 16384 halves (2 stages x 2 terms x 2 ksub x 128 x 16),
//       B region 16384 halves (2 stages x 2 terms x 32 x 128). 64KB total.
#define GEMM_SMEM_BYTES 65536

__device__ __forceinline__ void gemm_tc(
    const float* __restrict__ A, const float* __restrict__ Bm,
    float* __restrict__ Cm)
{
    extern __shared__ __align__(16) __nv_bfloat16 dsm[];
    __nv_bfloat16* sA = dsm;
    __nv_bfloat16* sB = dsm + 16384;
    const uint32_t baseA = cvta_sm(sA);
    const uint32_t baseB = cvta_sm(sB);

    const int tid  = threadIdx.x;
    const int lane = tid & 31;
    const int wid  = tid >> 5;
    const int wm   = wid >> 2;          // 0..1
    const int wn   = wid & 3;           // 0..3
    const int m0   = blockIdx.y * 128;
    const int n0   = blockIdx.x * 128;

    // loader indices
    const int kq    = tid & 7;          // A: k quad within 32 (k = kq*4)
    const int rbase = tid >> 3;         // A: row 0..31 (rows rbase+32i)
    const int nq    = tid & 31;         // B: n quad (n = nq*4)
    const int kb    = tid >> 5;         // B: k row 0..7 (rows kb+8i)
    const int ksubL = kq >> 2;
    const int chA   = (kq >> 1) & 1;
    const int eA    = (kq & 1) * 4;
    const int chB   = nq >> 1;
    const int eB    = (nq & 1) * 4;

    float4 pa[4], pb[4];
    const float* Abase = A + (size_t)(m0 + rbase)*Cc + kq*4;
    const float* Bbase = Bm + (size_t)kb*Cc + n0 + nq*4;

#pragma unroll
    for (int i = 0; i < 4; i++) {
        pa[i] = *(const float4*)(Abase + (size_t)i*32*Cc);
        pb[i] = *(const float4*)(Bbase + (size_t)i*8*Cc);
    }

    // store tile into stage s
    auto store_tile = [&](int s) {
#pragma unroll
        for (int i = 0; i < 4; i++) {
            int row = rbase + 32*i;
            int swz = chA ^ ((row >> 2) & 1);
            int offH = (((s*2 + 0)*2 + ksubL)*128 + row)*16 + swz*8 + eA;
            float4 v = pa[i];
            __nv_bfloat16 hx = __float2bfloat16_rn(v.x);
            __nv_bfloat16 hy = __float2bfloat16_rn(v.y);
            __nv_bfloat16 hz = __float2bfloat16_rn(v.z);
            __nv_bfloat16 hw = __float2bfloat16_rn(v.w);
            uint2 hi, lo;
            hi.x = packbf(v.x*0.f + __bfloat162float(hx), __bfloat162float(hy));
            hi.x = ((uint32_t)*(uint16_t*)&hy << 16) | *(uint16_t*)&hx;
            hi.y = ((uint32_t)*(uint16_t*)&hw << 16) | *(uint16_t*)&hz;
            lo.x = packbf(v.x - __bfloat162float(hx), v.y - __bfloat162float(hy));
            lo.y = packbf(v.z - __bfloat162float(hz), v.w - __bfloat162float(hw));
            *(uint2*)(sA + offH)        = hi;
            *(uint2*)(sA + offH + 4096) = lo;
        }
#pragma unroll
        for (int i = 0; i < 4; i++) {
            int kr = kb + 8*i;
            int off = ((s*2 + 0)*32 + kr)*128 + ((chB ^ (kr & 7))*8) + eB;
            float4 v = pb[i];
            __nv_bfloat16 hx = __float2bfloat16_rn(v.x);
            __nv_bfloat16 hy = __float2bfloat16_rn(v.y);
            __nv_bfloat16 hz = __float2bfloat16_rn(v.z);
            __nv_bfloat16 hw = __float2bfloat16_rn(v.w);
            uint2 hi, lo;
            hi.x = ((uint32_t)*(uint16_t*)&hy << 16) | *(uint16_t*)&hx;
            hi.y = ((uint32_t)*(uint16_t*)&hw << 16) | *(uint16_t*)&hz;
            lo.x = packbf(v.x - __bfloat162float(hx), v.y - __bfloat162float(hy));
            lo.y = packbf(v.z - __bfloat162float(hz), v.w - __bfloat162float(hw));
            *(uint2*)(sB + off)        = hi;
            *(uint2*)(sB + off + 4096) = lo;
        }
    };

    store_tile(0);
    __syncthreads();

    float acc[4][4][4];
#pragma unroll
    for (int i = 0; i < 4; i++)
#pragma unroll
        for (int j = 0; j < 4; j++)
#pragma unroll
            for (int e = 0; e < 4; e++) acc[i][j][e] = 0.f;

    // frag address helpers (lane-dependent, stage/ksub/term vary)
    const int rlA  = lane & 15;
    const int selA = lane >> 4;
    const int krB  = ((lane >> 3) & 1)*8 + (lane & 7);
    const int ncB  = lane >> 4;

    int stage = 0;
    const int NKT = Cc / 32;            // 64
    for (int kt = 0; kt < NKT; kt++) {
        if (kt + 1 < NKT) {
            const float* An = Abase + (size_t)(kt + 1)*32;
            const float* Bn = Bbase + (size_t)(kt + 1)*32*Cc;
#pragma unroll
            for (int i = 0; i < 4; i++) {
                pa[i] = *(const float4*)(An + (size_t)i*32*Cc);
                pb[i] = *(const float4*)(Bn + (size_t)i*8*Cc);
            }
        }
#pragma unroll
        for (int ksub = 0; ksub < 2; ksub++) {
            uint32_t Ah[4][4], Al[4][4], Bh[4][2], Bl[4][2];
#pragma unroll
            for (int i = 0; i < 4; i++) {
                int row = wm*64 + i*16 + rlA;
                int off = (((stage*2 + 0)*2 + ksub)*128 + row)*16
                        + ((selA ^ ((row >> 2) & 1))*8);
                ldsm_x4(baseA + (uint32_t)off*2, Ah[i]);
                ldsm_x4(baseA + (uint32_t)(off + 4096)*2, Al[i]);
            }
#pragma unroll
            for (int jj = 0; jj < 2; jj++) {
                int kr = ksub*16 + krB;
                int nchunk = wn*4 + jj*2 + ncB;
                int off = ((stage*2 + 0)*32 + kr)*128 + ((nchunk ^ (kr & 7))*8);
                uint32_t tmp[4];
                ldsm_x4t(baseB + (uint32_t)off*2, tmp);
                Bh[2*jj][0] = tmp[0]; Bh[2*jj][1] = tmp[1];
                Bh[2*jj+1][0] = tmp[2]; Bh[2*jj+1][1] = tmp[3];
                ldsm_x4t(baseB + (uint32_t)(off + 4096)*2, tmp);
                Bl[2*jj][0] = tmp[0]; Bl[2*jj][1] = tmp[1];
                Bl[2*jj+1][0] = tmp[2]; Bl[2*jj+1][1] = tmp[3];
            }
#pragma unroll
            for (int i = 0; i < 4; i++)
#pragma unroll
                for (int j = 0; j < 4; j++) {
                    mma_bf16(acc[i][j], Ah[i], Bh[j]);
                    mma_bf16(acc[i][j], Ah[i], Bl[j]);
                    mma_bf16(acc[i][j], Al[i], Bh[j]);
                }
        }
        if (kt + 1 < NKT) store_tile(stage ^ 1);
        __syncthreads();
        stage ^= 1;
    }

    // epilogue
    const int g = lane >> 2, tq = lane & 3;
#pragma unroll
    for (int i = 0; i < 4; i++) {
#pragma unroll
        for (int j = 0; j < 4; j++) {
            int row = m0 + wm*64 + i*16 + g;
            int col = n0 + wn*32 + j*8 + tq*2;
            *(float2*)(Cm + (size_t)row*Cc + col) =
                make_float2(acc[i][j][0], acc[i][j][1]);
            *(float2*)(Cm + (size_t)(row + 8)*Cc + col) =
                make_float2(acc[i][j][2], acc[i][j][3]);
        }
    }
}

__global__ __launch_bounds__(256) void k_gemm_qkv(
    const float* __restrict__ Wq, const float* __restrict__ Wk,
    const float* __restrict__ Wv)
{
    const float* A; const float* W; float* C;
    if (blockIdx.z == 0)      { A = s_xr; W = Wq; C = s_yq; }
    else if (blockIdx.z == 1) { A = s_xk; W = Wk; C = s_yk; }
    else                      { A = s_xv; W = Wv; C = s_yv; }
    gemm_tc(A, W, C);
}

__global__ __launch_bounds__(256) void k_gemm_o(
    const float* __restrict__ Wo, float* __restrict__ out)
{
    gemm_tc(s_on, Wo, out);
}

// ---------------- 4. LN (+RoPE) into head layout ----------------
__global__ __launch_bounds__(256) void k_lnqkv(
    const float* __restrict__ gr, const float* __restrict__ br_,
    const float* __restrict__ gk, const float* __restrict__ bk_,
    const float* __restrict__ gv, const float* __restrict__ bv_,
    const float* __restrict__ cosT, const float* __restrict__ sinT)
{
    int mode = blockIdx.y;
    const float* Y; const float* g; const float* bbv; float* out;
    if (mode == 0)      { Y = s_yq; g = gr; bbv = br_; out = s_qh; }
    else if (mode == 1) { Y = s_yk; g = gk; bbv = bk_; out = s_kh; }
    else                { Y = s_yv; g = gv; bbv = bv_; out = s_vh; }
    int row = blockIdx.x;
    int t = row & (Tt - 1), b = row >> 10;
    __shared__ float srow[Cc];
    __shared__ float red[64];
    const float* yr = Y + (size_t)row*Cc;
    float sum = 0.f, sq = 0.f, vals[8];
#pragma unroll
    for (int k = 0; k < 8; k++) {
        float v = yr[threadIdx.x + k*256];
        vals[k] = v; sum += v; sq = fmaf(v, v, sq);
    }
#pragma unroll
    for (int o = 16; o; o >>= 1) {
        sum += __shfl_xor_sync(0xffffffffu, sum, o);
        sq  += __shfl_xor_sync(0xffffffffu, sq,  o);
    }
    int w = threadIdx.x >> 5;
    if ((threadIdx.x & 31) == 0) { red[w] = sum; red[32 + w] = sq; }
    __syncthreads();
    if (threadIdx.x < 32) {
        float s1 = (threadIdx.x < 8) ? red[threadIdx.x] : 0.f;
        float s2 = (threadIdx.x < 8) ? red[32 + threadIdx.x] : 0.f;
#pragma unroll
        for (int o = 4; o; o >>= 1) {
            s1 += __shfl_xor_sync(0xffffffffu, s1, o);
            s2 += __shfl_xor_sync(0xffffffffu, s2, o);
        }
        if (threadIdx.x == 0) { red[0] = s1; red[32] = s2; }
    }
    __syncthreads();
    float mu  = red[0]  * (1.f/Cc);
    float var = red[32] * (1.f/Cc) - mu*mu;
    float inv = rsqrtf(var + 1e-5f);
#pragma unroll
    for (int k = 0; k < 8; k++) {
        int c = threadIdx.x + k*256;
        srow[c] = (vals[k] - mu)*inv*g[c] + bbv[c];
    }
    __syncthreads();
#pragma unroll
    for (int k = 0; k < 8; k++) {
        int c = threadIdx.x + k*256;
        int h = c >> 6, d = c & 63;
        float o;
        if (mode == 2) { o = srow[c]; }
        else if (d < 32) {
            float cc = cosT[t*32 + d], ss = sinT[t*32 + d];
            o = srow[c]*cc - srow[c + 32]*ss;
        } else {
            int d2 = d - 32;
            float cc = cosT[t*32 + d2], ss = sinT[t*32 + d2];
            o = srow[c - 32]*ss + srow[c]*cc;
        }
        out[(((size_t)(b*Hh + h)*Tt + t) << 6) + d] = o;
    }
}

// ---------------- 6. LN of attention output ----------------
__global__ __launch_bounds__(256) void k_lnplain(
    const float* __restrict__ gx, const float* __restrict__ bx)
{
    int row = blockIdx.x;
    __shared__ float red[64];
    const float* yr = s_att + (size_t)row*Cc;
    float sum = 0.f, sq = 0.f, vals[8];
#pragma unroll
    for (int k = 0; k < 8; k++) {
        float v = yr[threadIdx.x + k*256];
        vals[k] = v; sum += v; sq = fmaf(v, v, sq);
    }
#pragma unroll
    for (int o = 16; o; o >>= 1) {
        sum += __shfl_xor_sync(0xffffffffu, sum, o);
        sq  += __shfl_xor_sync(0xffffffffu, sq,  o);
    }
    int w = threadIdx.x >> 5;
    if ((threadIdx.x & 31) == 0) { red[w] = sum; red[32 + w] = sq; }
    __syncthreads();
    if (threadIdx.x < 32) {
        float s1 = (threadIdx.x < 8) ? red[threadIdx.x] : 0.f;
        float s2 = (threadIdx.x < 8) ? red[32 + threadIdx.x] : 0.f;
#pragma unroll
        for (int o = 4; o; o >>= 1) {
            s1 += __shfl_xor_sync(0xffffffffu, s1, o);
            s2 += __shfl_xor_sync(0xffffffffu, s2, o);
        }
        if (threadIdx.x == 0) { red[0] = s1; red[32] = s2; }
    }
    __syncthreads();
    float mu  = red[0]  * (1.f/Cc);
    float var = red[32] * (1.f/Cc) - mu*mu;
    float inv = rsqrtf(var + 1e-5f);
    float* orow = s_on + (size_t)row*Cc;
#pragma unroll
    for (int k = 0; k < 8; k++) {
        int c = threadIdx.x + k*256;
        orow[c] = (vals[k] - mu)*inv*gx[c] + bx[c];
    }
}

// ---------------- 5. causal flash attention, fp32 ----------------
__global__ __launch_bounds__(256) void k_attn()
{
    __shared__ __align__(16) float Qs[64][68];
    __shared__ __align__(16) float Kt[64][34];
    __shared__ __align__(16) float Vs[32][64];
    __shared__ float Ps[64][33];
    int qt = (int)gridDim.x - 1 - (int)blockIdx.x;
    int bh = blockIdx.y;
    const float* Qg = s_qh + (size_t)bh*Tt*64;
    const float* Kg = s_kh + (size_t)bh*Tt*64;
    const float* Vg = s_vh + (size_t)bh*Tt*64;
    int b = bh >> 5, h = bh & 31;
    int tid = threadIdx.x, tx = tid & 15, ty = tid >> 4;
    int q0 = qt * 64;

    for (int i = tid; i < 64*16; i += 256) {
        int r = i >> 4, c4 = (i & 15) << 2;
        *(float4*)&Qs[r][c4] = *(const float4*)(Qg + (size_t)(q0 + r)*64 + c4);
    }
    float accO[4][4];
    float mrow[4], lrow[4];
#pragma unroll
    for (int i = 0; i < 4; i++) {
        mrow[i] = -1e30f; lrow[i] = 0.f;
#pragma unroll
        for (int j = 0; j < 4; j++) accO[i][j] = 0.f;
    }
    __syncthreads();

    int nkb = (qt + 1) * 2;
    for (int kb = 0; kb < nkb; kb++) {
        int s0 = kb * 32;
        for (int i = tid; i < 32*16; i += 256) {
            int r = i >> 4, c4 = (i & 15) << 2;
            float4 kv = *(const float4*)(Kg + (size_t)(s0 + r)*64 + c4);
            Kt[c4 + 0][r] = kv.x; Kt[c4 + 1][r] = kv.y;
            Kt[c4 + 2][r] = kv.z; Kt[c4 + 3][r] = kv.w;
            *(float4*)&Vs[r][c4] = *(const float4*)(Vg + (size_t)(s0 + r)*64 + c4);
        }
        __syncthreads();

        float sc[4][2];
#pragma unroll
        for (int i = 0; i < 4; i++) { sc[i][0] = 0.f; sc[i][1] = 0.f; }
#pragma unroll 4
        for (int d = 0; d < 64; d++) {
            float2 kv = *(const float2*)&Kt[d][tx << 1];
#pragma unroll
            for (int i = 0; i < 4; i++) {
                float qv = Qs[ty*4 + i][d];
                sc[i][0] = fmaf(qv, kv.x, sc[i][0]);
                sc[i][1] = fmaf(qv, kv.y, sc[i][1]);
            }
        }
#pragma unroll
        for (int i = 0; i < 4; i++) {
            int qg = q0 + ty*4 + i;
            float s0v = sc[i][0] * 0.125f;
            float s1v = sc[i][1] * 0.125f;
            int kg0 = s0 + (tx << 1);
            if (kg0     > qg) s0v = -1e30f;
            if (kg0 + 1 > qg) s1v = -1e30f;
            float mx = fmaxf(s0v, s1v);
#pragma unroll
            for (int o = 8; o; o >>= 1) mx = fmaxf(mx, __shfl_xor_sync(0xffffffffu, mx, o));
            float mnew = fmaxf(mrow[i], mx);
            float alpha = __expf(mrow[i] - mnew);
            mrow[i] = mnew;
            float p0 = __expf(s0v - mnew);
            float p1 = __expf(s1v - mnew);
            float rs = p0 + p1;
#pragma unroll
            for (int o = 8; o; o >>= 1) rs += __shfl_xor_sync(0xffffffffu, rs, o);
            lrow[i] = lrow[i]*alpha + rs;
#pragma unroll
            for (int j = 0; j < 4; j++) accO[i][j] *= alpha;
            Ps[ty*4 + i][(tx << 1)]     = p0;
            Ps[ty*4 + i][(tx << 1) + 1] = p1;
        }
        __syncthreads();
#pragma unroll 8
        for (int s_ = 0; s_ < 32; s_++) {
            float4 vv = *(const float4*)&Vs[s_][tx << 2];
#pragma unroll
            for (int i = 0; i < 4; i++) {
                float p = Ps[ty*4 + i][s_];
                accO[i][0] = fmaf(p, vv.x, accO[i][0]);
                accO[i][1] = fmaf(p, vv.y, accO[i][1]);
                accO[i][2] = fmaf(p, vv.z, accO[i][2]);
                accO[i][3] = fmaf(p, vv.w, accO[i][3]);
            }
        }
        __syncthreads();
    }
#pragma unroll
    for (int i = 0; i < 4; i++) {
        float inv = 1.f / lrow[i];
        int t = q0 + ty*4 + i;
        float* op = s_att + (size_t)(b*Tt + t)*Cc + h*64 + (tx << 2);
        *(float4*)op = make_float4(accO[i][0]*inv, accO[i][1]*inv,
                                   accO[i][2]*inv, accO[i][3]*inv);
    }
}

// ---------------- launch ----------------
extern "C" void kernel_launch(void* const* d_in, const int* in_sizes, int n_in,
                              void* d_out, int out_size)
{
    (void)in_sizes; (void)n_in; (void)out_size;
    const float* x     = (const float*)d_in[0];
    const float* shift = (const float*)d_in[1];
    const float* maa_x = (const float*)d_in[2];
    const float* maa_r = (const float*)d_in[3];
    const float* maa_k = (const float*)d_in[4];
    const float* maa_v = (const float*)d_in[5];
    const float* w1    = (const float*)d_in[6];
    const float* w2    = (const float*)d_in[7];
    const float* Wq    = (const float*)d_in[8];
    const float* Wk    = (const float*)d_in[9];
    const float* Wv    = (const float*)d_in[10];
    const float* Wo    = (const float*)d_in[11];
    const float* g_r   = (const float*)d_in[12];
    const float* b_r   = (const float*)d_in[13];
    const float* g_k   = (const float*)d_in[14];
    const float* b_k   = (const float*)d_in[15];
    const float* g_v   = (const float*)d_in[16];
    const float* b_v   = (const float*)d_in[17];
    const float* g_x   = (const float*)d_in[18];
    const float* b_x   = (const float*)d_in[19];
    const float* cosT  = (const float*)d_in[20];
    const float* sinT  = (const float*)d_in[21];
    float* out = (float*)d_out;

    cudaFuncSetAttribute(k_gemm_qkv, cudaFuncAttributeMaxDynamicSharedMemorySize,
                         GEMM_SMEM_BYTES);
    cudaFuncSetAttribute(k_gemm_o, cudaFuncAttributeMaxDynamicSharedMemorySize,
                         GEMM_SMEM_BYTES);

    k_prelude<<<NT*Cc/256, 256>>>(x, shift, maa_x);
    k_lora1<<<NT/16, 96>>>(w1);
    k_mix<<<dim3(Cc/64, NT/16), 64>>>(x, w2, maa_r, maa_k, maa_v);
    k_gemm_qkv<<<dim3(16, 16, 3), 256, GEMM_SMEM_BYTES>>>(Wq, Wk, Wv);
    k_lnqkv<<<dim3(NT, 3), 256>>>(g_r, b_r, g_k, b_k, g_v, b_v, cosT, sinT);
    k_attn<<<dim3(16, Bb*Hh), 256>>>();
    k_lnplain<<<NT, 256>>>(g_x, b_x);
    k_gemm_o<<<dim3(16, 16), 256, GEMM_SMEM_BYTES>>>(Wo, out);
}

// round 5
// speedup vs baseline: 1.8624x; 1.2330x over previous
#include <cuda_runtime.h>
#include <cuda_bf16.h>
#include <math.h>
#include <stdint.h>

#define Bb 2
#define Tt 1024
#define Cc 2048
#define Hh 32
#define Dd 64
#define NT (Bb*Tt)        /* 2048 token rows */
#define L3 96             /* 3 * D_MIX_LORA */

// ---------------- scratch (device globals; allocation-free) ----------------
__device__ __align__(16) float s_dx[NT*Cc];
__device__ __align__(16) float s_xx[NT*Cc];
__device__ __align__(16) float s_h [NT*L3];
__device__ __align__(16) float s_xr[NT*Cc];
__device__ __align__(16) float s_xk[NT*Cc];
__device__ __align__(16) float s_xv[NT*Cc];
__device__ __align__(16) float s_yq[NT*Cc];
__device__ __align__(16) float s_yk[NT*Cc];
__device__ __align__(16) float s_yv[NT*Cc];
__device__ __align__(16) float s_qh[NT*Cc];   // [B,H,T,D]
__device__ __align__(16) float s_kh[NT*Cc];
__device__ __align__(16) float s_vh[NT*Cc];
__device__ __align__(16) float s_att[NT*Cc];  // [B,T,C]
__device__ __align__(16) float s_on[NT*Cc];

// ---------------- 1. shift + token-mix base ----------------
__global__ __launch_bounds__(256) void k_prelude(
    const float* __restrict__ x, const float* __restrict__ shift,
    const float* __restrict__ maa_x)
{
    int idx = blockIdx.x * 256 + threadIdx.x;
    int c  = idx & (Cc - 1);
    int bt = idx >> 11;
    int t  = bt & (Tt - 1);
    int b  = bt >> 10;
    float xv = x[idx];
    float xp = (t == 0) ? shift[b*Cc + c] : x[idx - Cc];
    float dx = xp - xv;
    s_dx[idx] = dx;
    s_xx[idx] = fmaf(dx, maa_x[c], xv);
}

// ---------------- 2. LoRA stage 1 ----------------
__global__ __launch_bounds__(96) void k_lora1(const float* __restrict__ w1)
{
    __shared__ float xs[16][128];
    int n0 = blockIdx.x * 16;
    int j  = threadIdx.x;
    float acc[16];
#pragma unroll
    for (int r = 0; r < 16; r++) acc[r] = 0.f;
    for (int k0 = 0; k0 < Cc; k0 += 128) {
        __syncthreads();
        for (int i = threadIdx.x; i < 16*128; i += 96) {
            int r = i >> 7, cc = i & 127;
            xs[r][cc] = s_xx[(n0 + r)*Cc + k0 + cc];
        }
        __syncthreads();
        for (int k = 0; k < 128; k++) {
            float wv = w1[(k0 + k)*L3 + j];
#pragma unroll
            for (int r = 0; r < 16; r++) acc[r] = fmaf(xs[r][k], wv, acc[r]);
        }
    }
#pragma unroll
    for (int r = 0; r < 16; r++) s_h[(n0 + r)*L3 + j] = tanhf(acc[r]);
}

// ---------------- 3. LoRA stage 2 + mixing ----------------
__global__ __launch_bounds__(64) void k_mix(
    const float* __restrict__ x, const float* __restrict__ w2,
    const float* __restrict__ maa_r, const float* __restrict__ maa_k,
    const float* __restrict__ maa_v)
{
    __shared__ float w2s[96][64];
    __shared__ float hs[16][96];
    int c0 = blockIdx.x * 64;
    int n0 = blockIdx.y * 16;
    int tid = threadIdx.x;
    for (int i = tid; i < 96*64; i += 64) {
        int rr = i >> 6, cc = i & 63;
        w2s[rr][cc] = w2[rr*Cc + c0 + cc];
    }
    for (int i = tid; i < 16*96; i += 64) {
        int rr = i / 96, jj = i % 96;
        hs[rr][jj] = s_h[(n0 + rr)*L3 + jj];
    }
    __syncthreads();
    int c = c0 + tid;
    float ar = maa_r[c], ak = maa_k[c], av = maa_v[c];
    for (int r = 0; r < 16; r++) {
        float m0 = 0.f, m1 = 0.f, m2 = 0.f;
#pragma unroll
        for (int i = 0; i < 32; i++) {
            m0 = fmaf(hs[r][i],      w2s[i][tid],      m0);
            m1 = fmaf(hs[r][32 + i], w2s[32 + i][tid], m1);
            m2 = fmaf(hs[r][64 + i], w2s[64 + i][tid], m2);
        }
        size_t idx = (size_t)(n0 + r)*Cc + c;
        float xf = x[idx], dxf = s_dx[idx];
        s_xr[idx] = fmaf(dxf, ar + m0, xf);
        s_xk[idx] = fmaf(dxf, ak + m1, xf);
        s_xv[idx] = fmaf(dxf, av + m2, xf);
    }
}

// ============ shared mma helpers ============
__device__ __forceinline__ uint32_t cvta_sm(const void* p) {
    return (uint32_t)__cvta_generic_to_shared(p);
}
__device__ __forceinline__ void ldsm_x4(uint32_t addr, uint32_t* r) {
    asm volatile("ldmatrix.sync.aligned.m8n8.x4.shared.b16 {%0,%1,%2,%3},[%4];"
        : "=r"(r[0]), "=r"(r[1]), "=r"(r[2]), "=r"(r[3]) : "r"(addr));
}
__device__ __forceinline__ void ldsm_x4t(uint32_t addr, uint32_t* r) {
    asm volatile("ldmatrix.sync.aligned.m8n8.x4.trans.shared.b16 {%0,%1,%2,%3},[%4];"
        : "=r"(r[0]), "=r"(r[1]), "=r"(r[2]), "=r"(r[3]) : "r"(addr));
}
__device__ __forceinline__ void mma_bf16(float* d, const uint32_t* a, const uint32_t* b) {
    asm volatile(
        "mma.sync.aligned.m16n8k16.row.col.f32.bf16.bf16.f32 "
        "{%0,%1,%2,%3},{%4,%5,%6,%7},{%8,%9},{%0,%1,%2,%3};"
        : "+f"(d[0]), "+f"(d[1]), "+f"(d[2]), "+f"(d[3])
        : "r"(a[0]), "r"(a[1]), "r"(a[2]), "r"(a[3]), "r"(b[0]), "r"(b[1]));
}
__device__ __forceinline__ uint32_t packbf(float x, float y) {
    __nv_bfloat162 h = __floats2bfloat162_rn(x, y);
    return *(uint32_t*)&h;
}
__device__ __forceinline__ uint32_t pack_hi2(float x, float y, float& rx, float& ry) {
    __nv_bfloat16 hx = __float2bfloat16_rn(x), hy = __float2bfloat16_rn(y);
    rx = x - __bfloat162float(hx);
    ry = y - __bfloat162float(hy);
    return ((uint32_t)*(uint16_t*)&hy << 16) | *(uint16_t*)&hx;
}

// ============ tensor-core GEMM: C = A @ B, 2048^3, 3x-bf16 split ============
#define GEMM_SMEM_BYTES 65536

__device__ __forceinline__ void gemm_tc(
    const float* __restrict__ A, const float* __restrict__ Bm,
    float* __restrict__ Cm)
{
    extern __shared__ __align__(16) __nv_bfloat16 dsm[];
    __nv_bfloat16* sA = dsm;
    __nv_bfloat16* sB = dsm + 16384;
    const uint32_t baseA = cvta_sm(sA);
    const uint32_t baseB = cvta_sm(sB);

    const int tid  = threadIdx.x;
    const int lane = tid & 31;
    const int wid  = tid >> 5;
    const int wm   = wid >> 2;
    const int wn   = wid & 3;
    const int m0   = blockIdx.y * 128;
    const int n0   = blockIdx.x * 128;

    const int kq    = tid & 7;
    const int rbase = tid >> 3;
    const int nq    = tid & 31;
    const int kb    = tid >> 5;
    const int ksubL = kq >> 2;
    const int chA   = (kq >> 1) & 1;
    const int eA    = (kq & 1) * 4;
    const int chB   = nq >> 1;
    const int eB    = (nq & 1) * 4;

    float4 pa[4], pb[4];
    const float* Abase = A + (size_t)(m0 + rbase)*Cc + kq*4;
    const float* Bbase = Bm + (size_t)kb*Cc + n0 + nq*4;

#pragma unroll
    for (int i = 0; i < 4; i++) {
        pa[i] = *(const float4*)(Abase + (size_t)i*32*Cc);
        pb[i] = *(const float4*)(Bbase + (size_t)i*8*Cc);
    }

    auto store_tile = [&](int s) {
#pragma unroll
        for (int i = 0; i < 4; i++) {
            int row = rbase + 32*i;
            int swz = chA ^ ((row >> 2) & 1);
            int offH = (((s*2 + 0)*2 + ksubL)*128 + row)*16 + swz*8 + eA;
            float4 v = pa[i];
            float r0,r1,r2,r3;
            uint2 hi, lo;
            hi.x = pack_hi2(v.x, v.y, r0, r1);
            hi.y = pack_hi2(v.z, v.w, r2, r3);
            lo.x = packbf(r0, r1);
            lo.y = packbf(r2, r3);
            *(uint2*)(sA + offH)        = hi;
            *(uint2*)(sA + offH + 4096) = lo;
        }
#pragma unroll
        for (int i = 0; i < 4; i++) {
            int kr = kb + 8*i;
            int off = ((s*2 + 0)*32 + kr)*128 + ((chB ^ (kr & 7))*8) + eB;
            float4 v = pb[i];
            float r0,r1,r2,r3;
            uint2 hi, lo;
            hi.x = pack_hi2(v.x, v.y, r0, r1);
            hi.y = pack_hi2(v.z, v.w, r2, r3);
            lo.x = packbf(r0, r1);
            lo.y = packbf(r2, r3);
            *(uint2*)(sB + off)        = hi;
            *(uint2*)(sB + off + 4096) = lo;
        }
    };

    store_tile(0);
    __syncthreads();

    float acc[4][4][4];
#pragma unroll
    for (int i = 0; i < 4; i++)
#pragma unroll
        for (int j = 0; j < 4; j++)
#pragma unroll
            for (int e = 0; e < 4; e++) acc[i][j][e] = 0.f;

    const int rlA  = lane & 15;
    const int selA = lane >> 4;
    const int krB  = ((lane >> 3) & 1)*8 + (lane & 7);
    const int ncB  = lane >> 4;

    int stage = 0;
    const int NKT = Cc / 32;
    for (int kt = 0; kt < NKT; kt++) {
        if (kt + 1 < NKT) {
            const float* An = Abase + (size_t)(kt + 1)*32;
            const float* Bn = Bbase + (size_t)(kt + 1)*32*Cc;
#pragma unroll
            for (int i = 0; i < 4; i++) {
                pa[i] = *(const float4*)(An + (size_t)i*32*Cc);
                pb[i] = *(const float4*)(Bn + (size_t)i*8*Cc);
            }
        }
#pragma unroll
        for (int ksub = 0; ksub < 2; ksub++) {
            uint32_t Ah[4][4], Al[4][4], Bh[4][2], Bl[4][2];
#pragma unroll
            for (int i = 0; i < 4; i++) {
                int row = wm*64 + i*16 + rlA;
                int off = (((stage*2 + 0)*2 + ksub)*128 + row)*16
                        + ((selA ^ ((row >> 2) & 1))*8);
                ldsm_x4(baseA + (uint32_t)off*2, Ah[i]);
                ldsm_x4(baseA + (uint32_t)(off + 4096)*2, Al[i]);
            }
#pragma unroll
            for (int jj = 0; jj < 2; jj++) {
                int kr = ksub*16 + krB;
                int nchunk = wn*4 + jj*2 + ncB;
                int off = ((stage*2 + 0)*32 + kr)*128 + ((nchunk ^ (kr & 7))*8);
                uint32_t tmp[4];
                ldsm_x4t(baseB + (uint32_t)off*2, tmp);
                Bh[2*jj][0] = tmp[0]; Bh[2*jj][1] = tmp[1];
                Bh[2*jj+1][0] = tmp[2]; Bh[2*jj+1][1] = tmp[3];
                ldsm_x4t(baseB + (uint32_t)(off + 4096)*2, tmp);
                Bl[2*jj][0] = tmp[0]; Bl[2*jj][1] = tmp[1];
                Bl[2*jj+1][0] = tmp[2]; Bl[2*jj+1][1] = tmp[3];
            }
#pragma unroll
            for (int i = 0; i < 4; i++)
#pragma unroll
                for (int j = 0; j < 4; j++) {
                    mma_bf16(acc[i][j], Ah[i], Bh[j]);
                    mma_bf16(acc[i][j], Ah[i], Bl[j]);
                    mma_bf16(acc[i][j], Al[i], Bh[j]);
                }
        }
        if (kt + 1 < NKT) store_tile(stage ^ 1);
        __syncthreads();
        stage ^= 1;
    }

    const int g = lane >> 2, tq = lane & 3;
#pragma unroll
    for (int i = 0; i < 4; i++) {
#pragma unroll
        for (int j = 0; j < 4; j++) {
            int row = m0 + wm*64 + i*16 + g;
            int col = n0 + wn*32 + j*8 + tq*2;
            *(float2*)(Cm + (size_t)row*Cc + col) =
                make_float2(acc[i][j][0], acc[i][j][1]);
            *(float2*)(Cm + (size_t)(row + 8)*Cc + col) =
                make_float2(acc[i][j][2], acc[i][j][3]);
        }
    }
}

__global__ __launch_bounds__(256) void k_gemm_qkv(
    const float* __restrict__ Wq, const float* __restrict__ Wk,
    const float* __restrict__ Wv)
{
    const float* A; const float* W; float* C;
    if (blockIdx.z == 0)      { A = s_xr; W = Wq; C = s_yq; }
    else if (blockIdx.z == 1) { A = s_xk; W = Wk; C = s_yk; }
    else                      { A = s_xv; W = Wv; C = s_yv; }
    gemm_tc(A, W, C);
}

__global__ __launch_bounds__(256) void k_gemm_o(
    const float* __restrict__ Wo, float* __restrict__ out)
{
    gemm_tc(s_on, Wo, out);
}

// ---------------- 4. LN (+RoPE) into head layout ----------------
__global__ __launch_bounds__(256) void k_lnqkv(
    const float* __restrict__ gr, const float* __restrict__ br_,
    const float* __restrict__ gk, const float* __restrict__ bk_,
    const float* __restrict__ gv, const float* __restrict__ bv_,
    const float* __restrict__ cosT, const float* __restrict__ sinT)
{
    int mode = blockIdx.y;
    const float* Y; const float* g; const float* bbv; float* out;
    if (mode == 0)      { Y = s_yq; g = gr; bbv = br_; out = s_qh; }
    else if (mode == 1) { Y = s_yk; g = gk; bbv = bk_; out = s_kh; }
    else                { Y = s_yv; g = gv; bbv = bv_; out = s_vh; }
    int row = blockIdx.x;
    int t = row & (Tt - 1), b = row >> 10;
    __shared__ float srow[Cc];
    __shared__ float red[64];
    const float* yr = Y + (size_t)row*Cc;
    float sum = 0.f, sq = 0.f, vals[8];
#pragma unroll
    for (int k = 0; k < 8; k++) {
        float v = yr[threadIdx.x + k*256];
        vals[k] = v; sum += v; sq = fmaf(v, v, sq);
    }
#pragma unroll
    for (int o = 16; o; o >>= 1) {
        sum += __shfl_xor_sync(0xffffffffu, sum, o);
        sq  += __shfl_xor_sync(0xffffffffu, sq,  o);
    }
    int w = threadIdx.x >> 5;
    if ((threadIdx.x & 31) == 0) { red[w] = sum; red[32 + w] = sq; }
    __syncthreads();
    if (threadIdx.x < 32) {
        float s1 = (threadIdx.x < 8) ? red[threadIdx.x] : 0.f;
        float s2 = (threadIdx.x < 8) ? red[32 + threadIdx.x] : 0.f;
#pragma unroll
        for (int o = 4; o; o >>= 1) {
            s1 += __shfl_xor_sync(0xffffffffu, s1, o);
            s2 += __shfl_xor_sync(0xffffffffu, s2, o);
        }
        if (threadIdx.x == 0) { red[0] = s1; red[32] = s2; }
    }
    __syncthreads();
    float mu  = red[0]  * (1.f/Cc);
    float var = red[32] * (1.f/Cc) - mu*mu;
    float inv = rsqrtf(var + 1e-5f);
#pragma unroll
    for (int k = 0; k < 8; k++) {
        int c = threadIdx.x + k*256;
        srow[c] = (vals[k] - mu)*inv*g[c] + bbv[c];
    }
    __syncthreads();
#pragma unroll
    for (int k = 0; k < 8; k++) {
        int c = threadIdx.x + k*256;
        int h = c >> 6, d = c & 63;
        float o;
        if (mode == 2) { o = srow[c]; }
        else if (d < 32) {
            float cc = cosT[t*32 + d], ss = sinT[t*32 + d];
            o = srow[c]*cc - srow[c + 32]*ss;
        } else {
            int d2 = d - 32;
            float cc = cosT[t*32 + d2], ss = sinT[t*32 + d2];
            o = srow[c - 32]*ss + srow[c]*cc;
        }
        out[(((size_t)(b*Hh + h)*Tt + t) << 6) + d] = o;
    }
}

// ---------------- 6. LN of attention output ----------------
__global__ __launch_bounds__(256) void k_lnplain(
    const float* __restrict__ gx, const float* __restrict__ bx)
{
    int row = blockIdx.x;
    __shared__ float red[64];
    const float* yr = s_att + (size_t)row*Cc;
    float sum = 0.f, sq = 0.f, vals[8];
#pragma unroll
    for (int k = 0; k < 8; k++) {
        float v = yr[threadIdx.x + k*256];
        vals[k] = v; sum += v; sq = fmaf(v, v, sq);
    }
#pragma unroll
    for (int o = 16; o; o >>= 1) {
        sum += __shfl_xor_sync(0xffffffffu, sum, o);
        sq  += __shfl_xor_sync(0xffffffffu, sq,  o);
    }
    int w = threadIdx.x >> 5;
    if ((threadIdx.x & 31) == 0) { red[w] = sum; red[32 + w] = sq; }
    __syncthreads();
    if (threadIdx.x < 32) {
        float s1 = (threadIdx.x < 8) ? red[threadIdx.x] : 0.f;
        float s2 = (threadIdx.x < 8) ? red[32 + threadIdx.x] : 0.f;
#pragma unroll
        for (int o = 4; o; o >>= 1) {
            s1 += __shfl_xor_sync(0xffffffffu, s1, o);
            s2 += __shfl_xor_sync(0xffffffffu, s2, o);
        }
        if (threadIdx.x == 0) { red[0] = s1; red[32] = s2; }
    }
    __syncthreads();
    float mu  = red[0]  * (1.f/Cc);
    float var = red[32] * (1.f/Cc) - mu*mu;
    float inv = rsqrtf(var + 1e-5f);
    float* orow = s_on + (size_t)row*Cc;
#pragma unroll
    for (int k = 0; k < 8; k++) {
        int c = threadIdx.x + k*256;
        orow[c] = (vals[k] - mu)*inv*gx[c] + bx[c];
    }
}

// ======== 5. causal flash attention, tensor cores, 3x-bf16 split ========
// BM=64 (4 warps x 16 rows), BN=64, D=64. 128 threads.
__global__ __launch_bounds__(128) void k_attn_tc()
{
    __shared__ __align__(16) __nv_bfloat16 sQ[2][4096];  // hi, lo; [row][col] swizzled
    __shared__ __align__(16) __nv_bfloat16 sK[2][4096];
    __shared__ __align__(16) __nv_bfloat16 sV[2][4096];

    const int qt  = (int)gridDim.x - 1 - (int)blockIdx.x;  // heavy tiles first
    const int bh  = blockIdx.y;
    const int b   = bh >> 5, h = bh & 31;
    const int tid = threadIdx.x, lane = tid & 31, w = tid >> 5;
    const int q0  = qt * 64;
    const float* Qg = s_qh + (size_t)bh*Tt*64;
    const float* Kg = s_kh + (size_t)bh*Tt*64;
    const float* Vg = s_vh + (size_t)bh*Tt*64;
    const uint32_t bQ0 = cvta_sm(sQ[0]), bQ1 = cvta_sm(sQ[1]);
    const uint32_t bK0 = cvta_sm(sK[0]), bK1 = cvta_sm(sK[1]);
    const uint32_t bV0 = cvta_sm(sV[0]), bV1 = cvta_sm(sV[1]);

    // ---- Q tile -> smem hi/lo ----
#pragma unroll
    for (int i = 0; i < 4; i++) {
        int seg = tid + i*128;
        int row = seg >> 3, ch = seg & 7;
        const float* src = Qg + (size_t)(q0 + row)*64 + ch*8;
        float4 v0 = *(const float4*)src, v1 = *(const float4*)(src + 4);
        float r0,r1,r2,r3,r4,r5,r6,r7;
        uint4 hi, lo;
        hi.x = pack_hi2(v0.x, v0.y, r0, r1);
        hi.y = pack_hi2(v0.z, v0.w, r2, r3);
        hi.z = pack_hi2(v1.x, v1.y, r4, r5);
        hi.w = pack_hi2(v1.z, v1.w, r6, r7);
        lo.x = packbf(r0, r1); lo.y = packbf(r2, r3);
        lo.z = packbf(r4, r5); lo.w = packbf(r6, r7);
        int off = (row*8 + (ch ^ (row & 7)))*8;
        *(uint4*)&sQ[0][off] = hi;
        *(uint4*)&sQ[1][off] = lo;
    }
    __syncthreads();

    // ---- Q A-frags (held for whole kernel) ----
    uint32_t qh[4][4], ql[4][4];
    const int g8 = lane >> 3, rr8 = lane & 7;
#pragma unroll
    for (int kk = 0; kk < 4; kk++) {
        int row = w*16 + (g8 & 1)*8 + rr8;
        int ch  = kk*2 + (g8 >> 1);
        uint32_t off = (uint32_t)(row*8 + (ch ^ (row & 7)))*16;
        ldsm_x4(bQ0 + off, qh[kk]);
        ldsm_x4(bQ1 + off, ql[kk]);
    }

    float o[8][4];
#pragma unroll
    for (int j = 0; j < 8; j++)
#pragma unroll
        for (int e = 0; e < 4; e++) o[j][e] = 0.f;
    float m0 = -1e30f, m1 = -1e30f, l0 = 0.f, l1 = 0.f;

    for (int kt = 0; kt <= qt; kt++) {
        int s0 = kt * 64;
        // prefetch K/V tile into registers
        float4 kvreg[8][2];
#pragma unroll
        for (int i = 0; i < 4; i++) {
            int seg = tid + i*128;
            int row = seg >> 3, ch = seg & 7;
            const float* ks = Kg + (size_t)(s0 + row)*64 + ch*8;
            const float* vs = Vg + (size_t)(s0 + row)*64 + ch*8;
            kvreg[i][0]   = *(const float4*)ks; kvreg[i][1]   = *(const float4*)(ks + 4);
            kvreg[i+4][0] = *(const float4*)vs; kvreg[i+4][1] = *(const float4*)(vs + 4);
        }
        __syncthreads();   // previous tile fully consumed
#pragma unroll
        for (int i = 0; i < 8; i++) {
            int seg = tid + (i & 3)*128;
            int row = seg >> 3, ch = seg & 7;
            int off = (row*8 + (ch ^ (row & 7)))*8;
            float r0,r1,r2,r3,r4,r5,r6,r7;
            uint4 hi, lo;
            hi.x = pack_hi2(kvreg[i][0].x, kvreg[i][0].y, r0, r1);
            hi.y = pack_hi2(kvreg[i][0].z, kvreg[i][0].w, r2, r3);
            hi.z = pack_hi2(kvreg[i][1].x, kvreg[i][1].y, r4, r5);
            hi.w = pack_hi2(kvreg[i][1].z, kvreg[i][1].w, r6, r7);
            lo.x = packbf(r0, r1); lo.y = packbf(r2, r3);
            lo.z = packbf(r4, r5); lo.w = packbf(r6, r7);
            __nv_bfloat16* dh = (i < 4) ? sK[0] : sV[0];
            __nv_bfloat16* dl = (i < 4) ? sK[1] : sV[1];
            *(uint4*)&dh[off] = hi;
            *(uint4*)&dl[off] = lo;
        }
        __syncthreads();

        // ---- S = Q K^T (3-term split) ----
        float c[8][4];
#pragma unroll
        for (int j = 0; j < 8; j++)
#pragma unroll
            for (int e = 0; e < 4; e++) c[j][e] = 0.f;
#pragma unroll
        for (int kk = 0; kk < 4; kk++) {
            uint32_t kbh[4][4], kbl[4][4];
#pragma unroll
            for (int u = 0; u < 4; u++) {
                int row = u*16 + (g8 >> 1)*8 + rr8;
                int ch  = kk*2 + (g8 & 1);
                uint32_t off = (uint32_t)(row*8 + (ch ^ (row & 7)))*16;
                ldsm_x4(bK0 + off, kbh[u]);
                ldsm_x4(bK1 + off, kbl[u]);
            }
#pragma unroll
            for (int u = 0; u < 4; u++) {
                mma_bf16(c[2*u],   qh[kk], &kbh[u][0]);
                mma_bf16(c[2*u],   qh[kk], &kbl[u][0]);
                mma_bf16(c[2*u],   ql[kk], &kbh[u][0]);
                mma_bf16(c[2*u+1], qh[kk], &kbh[u][2]);
                mma_bf16(c[2*u+1], qh[kk], &kbl[u][2]);
                mma_bf16(c[2*u+1], ql[kk], &kbh[u][2]);
            }
        }
        // scale + causal mask
        const int rl0 = w*16 + (lane >> 2);
#pragma unroll
        for (int j = 0; j < 8; j++)
#pragma unroll
            for (int e = 0; e < 4; e++) c[j][e] *= 0.125f;
        if (kt == qt) {
#pragma unroll
            for (int j = 0; j < 8; j++) {
                int col = j*8 + 2*(lane & 3);
                if (col     > rl0)     c[j][0] = -1e30f;
                if (col + 1 > rl0)     c[j][1] = -1e30f;
                if (col     > rl0 + 8) c[j][2] = -1e30f;
                if (col + 1 > rl0 + 8) c[j][3] = -1e30f;
            }
        }
        // ---- online softmax ----
        float mx0 = -1e30f, mx1 = -1e30f;
#pragma unroll
        for (int j = 0; j < 8; j++) {
            mx0 = fmaxf(mx0, fmaxf(c[j][0], c[j][1]));
            mx1 = fmaxf(mx1, fmaxf(c[j][2], c[j][3]));
        }
        mx0 = fmaxf(mx0, __shfl_xor_sync(0xffffffffu, mx0, 1));
        mx0 = fmaxf(mx0, __shfl_xor_sync(0xffffffffu, mx0, 2));
        mx1 = fmaxf(mx1, __shfl_xor_sync(0xffffffffu, mx1, 1));
        mx1 = fmaxf(mx1, __shfl_xor_sync(0xffffffffu, mx1, 2));
        float mn0 = fmaxf(m0, mx0), mn1 = fmaxf(m1, mx1);
        float a0 = __expf(m0 - mn0), a1 = __expf(m1 - mn1);
        m0 = mn0; m1 = mn1;

        uint32_t ph[4][4], pl[4][4];
        float rs0 = 0.f, rs1 = 0.f;
#pragma unroll
        for (int t = 0; t < 4; t++) {
            float p00 = __expf(c[2*t][0]   - mn0), p01 = __expf(c[2*t][1]   - mn0);
            float p02 = __expf(c[2*t][2]   - mn1), p03 = __expf(c[2*t][3]   - mn1);
            float p10 = __expf(c[2*t+1][0] - mn0), p11 = __expf(c[2*t+1][1] - mn0);
            float p12 = __expf(c[2*t+1][2] - mn1), p13 = __expf(c[2*t+1][3] - mn1);
            rs0 += p00 + p01 + p10 + p11;
            rs1 += p02 + p03 + p12 + p13;
            float e0, e1;
            ph[t][0] = pack_hi2(p00, p01, e0, e1); pl[t][0] = packbf(e0, e1);
            ph[t][1] = pack_hi2(p02, p03, e0, e1); pl[t][1] = packbf(e0, e1);
            ph[t][2] = pack_hi2(p10, p11, e0, e1); pl[t][2] = packbf(e0, e1);
            ph[t][3] = pack_hi2(p12, p13, e0, e1); pl[t][3] = packbf(e0, e1);
        }
        rs0 += __shfl_xor_sync(0xffffffffu, rs0, 1);
        rs0 += __shfl_xor_sync(0xffffffffu, rs0, 2);
        rs1 += __shfl_xor_sync(0xffffffffu, rs1, 1);
        rs1 += __shfl_xor_sync(0xffffffffu, rs1, 2);
        l0 = l0*a0 + rs0;
        l1 = l1*a1 + rs1;
#pragma unroll
        for (int j = 0; j < 8; j++) {
            o[j][0] *= a0; o[j][1] *= a0;
            o[j][2] *= a1; o[j][3] *= a1;
        }
        // ---- O += P V (3-term split) ----
#pragma unroll
        for (int t = 0; t < 4; t++) {
#pragma unroll
            for (int u = 0; u < 4; u++) {
                int row = t*16 + (g8 & 1)*8 + rr8;
                int ch  = u*2 + (g8 >> 1);
                uint32_t off = (uint32_t)(row*8 + (ch ^ (row & 7)))*16;
                uint32_t vh_[4], vl_[4];
                ldsm_x4t(bV0 + off, vh_);
                ldsm_x4t(bV1 + off, vl_);
                mma_bf16(o[2*u],   ph[t], &vh_[0]);
                mma_bf16(o[2*u],   pl[t], &vh_[0]);
                mma_bf16(o[2*u],   ph[t], &vl_[0]);
                mma_bf16(o[2*u+1], ph[t], &vh_[2]);
                mma_bf16(o[2*u+1], pl[t], &vh_[2]);
                mma_bf16(o[2*u+1], ph[t], &vl_[2]);
            }
        }
    }

    // ---- epilogue ----
    float inv0 = 1.f / l0, inv1 = 1.f / l1;
    int rg0 = q0 + w*16 + (lane >> 2);
    float* base0 = s_att + (size_t)(b*Tt + rg0)*Cc + h*64;
    float* base1 = base0 + (size_t)8*Cc;
#pragma unroll
    for (int j = 0; j < 8; j++) {
        int colo = j*8 + 2*(lane & 3);
        *(float2*)(base0 + colo) = make_float2(o[j][0]*inv0, o[j][1]*inv0);
        *(float2*)(base1 + colo) = make_float2(o[j][2]*inv1, o[j][3]*inv1);
    }
}

// ---------------- launch ----------------
extern "C" void kernel_launch(void* const* d_in, const int* in_sizes, int n_in,
                              void* d_out, int out_size)
{
    (void)in_sizes; (void)n_in; (void)out_size;
    const float* x     = (const float*)d_in[0];
    const float* shift = (const float*)d_in[1];
    const float* maa_x = (const float*)d_in[2];
    const float* maa_r = (const float*)d_in[3];
    const float* maa_k = (const float*)d_in[4];
    const float* maa_v = (const float*)d_in[5];
    const float* w1    = (const float*)d_in[6];
    const float* w2    = (const float*)d_in[7];
    const float* Wq    = (const float*)d_in[8];
    const float* Wk    = (const float*)d_in[9];
    const float* Wv    = (const float*)d_in[10];
    const float* Wo    = (const float*)d_in[11];
    const float* g_r   = (const float*)d_in[12];
    const float* b_r   = (const float*)d_in[13];
    const float* g_k   = (const float*)d_in[14];
    const float* b_k   = (const float*)d_in[15];
    const float* g_v   = (const float*)d_in[16];
    const float* b_v   = (const float*)d_in[17];
    const float* g_x   = (const float*)d_in[18];
    const float* b_x   = (const float*)d_in[19];
    const float* cosT  = (const float*)d_in[20];
    const float* sinT  = (const float*)d_in[21];
    float* out = (float*)d_out;

    cudaFuncSetAttribute(k_gemm_qkv, cudaFuncAttributeMaxDynamicSharedMemorySize,
                         GEMM_SMEM_BYTES);
    cudaFuncSetAttribute(k_gemm_o, cudaFuncAttributeMaxDynamicSharedMemorySize,
                         GEMM_SMEM_BYTES);

    k_prelude<<<NT*Cc/256, 256>>>(x, shift, maa_x);
    k_lora1<<<NT/16, 96>>>(w1);
    k_mix<<<dim3(Cc/64, NT/16), 64>>>(x, w2, maa_r, maa_k, maa_v);
    k_gemm_qkv<<<dim3(16, 16, 3), 256, GEMM_SMEM_BYTES>>>(Wq, Wk, Wv);
    k_lnqkv<<<dim3(NT, 3), 256>>>(g_r, b_r, g_k, b_k, g_v, b_v, cosT, sinT);
    k_attn_tc<<<dim3(16, Bb*Hh), 128>>>();
    k_lnplain<<<NT, 256>>>(g_x, b_x);
    k_gemm_o<<<dim3(16, 16), 256, GEMM_SMEM_BYTES>>>(Wo, out);
}